// round 14
// baseline (speedup 1.0000x reference)
#include <cuda_runtime.h>
#include <cuda_fp16.h>
#include <math.h>
#include <stdint.h>

#define NTHREADS 512
#define NWARPS 16
#define TILE_M 256     // 16 warps x 16 points

// fixed problem geometry
#define C_STRIDE 2097152ULL     // 256*256*32
#define B_STRIDE 67108864ULL    // 32*256*256*32
#define I_STRIDE 8192
#define J_STRIDE 32

struct __align__(16) Smem {
  // bf16 k16 banks (z, r): uint2 per (nt,kf4,lane) -> 8KB each
  unsigned wz_h16[2048];
  unsigned wr_h16[2048];
  unsigned wz_x16[2048];
  unsigned wr_x16[2048];
  // tf32 k8 banks (q, dec): uint2 per (nt,kf8,lane)
  unsigned wq_h[4096];   // 16KB
  unsigned wq_x[4096];
  unsigned wd_h[2048];   // 8KB
  unsigned wd_x[2048];
  // xproj fp16x2: [warp][entry 0-27 (z0-7,r8-15,q16-23,dec24-27)][lane][2]
  unsigned xp[NWARPS][28][32][2];
  float bz[64], br[64], bq[64], bd1[32];
  float Wd2[96], bd2[4];
};

__device__ __forceinline__ float tanh_hw(float x) {
  float y;
  asm("tanh.approx.f32 %0, %1;" : "=f"(y) : "f"(x));
  return y;
}
__device__ __forceinline__ float sigm(float x) {
  return fmaf(0.5f, tanh_hw(0.5f * x), 0.5f);
}
__device__ __forceinline__ unsigned cvt_tf32(float f) {
  unsigned u;
  asm("cvt.rna.tf32.f32 %0, %1;" : "=r"(u) : "f"(f));
  return u;
}
// pack two floats -> bf16x2 (lo in low half)
__device__ __forceinline__ unsigned packbf(float lo_, float hi_) {
  unsigned r;
  asm("cvt.rn.bf16x2.f32 %0, %1, %2;" : "=r"(r) : "f"(hi_), "f"(lo_));
  return r;
}

// ---- fp16 xp store/load ----
__device__ __forceinline__ void xp_store(unsigned* dst, const float d[4]) {
  __half2 a = __floats2half2_rn(d[0], d[1]);
  __half2 b = __floats2half2_rn(d[2], d[3]);
  dst[0] = *reinterpret_cast<unsigned*>(&a);
  dst[1] = *reinterpret_cast<unsigned*>(&b);
}
__device__ __forceinline__ void xp_load(float d[4], const unsigned* src) {
  uint2 v = *reinterpret_cast<const uint2*>(src);
  __half2 a = *reinterpret_cast<__half2*>(&v.x);
  __half2 b = *reinterpret_cast<__half2*>(&v.y);
  float2 fa = __half22float2(a), fb = __half22float2(b);
  d[0] = fa.x; d[1] = fa.y; d[2] = fb.x; d[3] = fb.y;
}

// m16n8k8 tf32 MMA
__device__ __forceinline__ void mma_tf32(float d[4], const unsigned a[4], uint2 b) {
  asm volatile(
    "mma.sync.aligned.m16n8k8.row.col.f32.tf32.tf32.f32 "
    "{%0,%1,%2,%3}, {%4,%5,%6,%7}, {%8,%9}, {%0,%1,%2,%3};"
    : "+f"(d[0]), "+f"(d[1]), "+f"(d[2]), "+f"(d[3])
    : "r"(a[0]), "r"(a[1]), "r"(a[2]), "r"(a[3]), "r"(b.x), "r"(b.y));
}
// m16n8k16 bf16 MMA
__device__ __forceinline__ void mma_bf16(float d[4], const unsigned a[4], uint2 b) {
  asm volatile(
    "mma.sync.aligned.m16n8k16.row.col.f32.bf16.bf16.f32 "
    "{%0,%1,%2,%3}, {%4,%5,%6,%7}, {%8,%9}, {%0,%1,%2,%3};"
    : "+f"(d[0]), "+f"(d[1]), "+f"(d[2]), "+f"(d[3])
    : "r"(a[0]), "r"(a[1]), "r"(a[2]), "r"(a[3]), "r"(b.x), "r"(b.y));
}

// tf32 K=64 gemm: 8 MMAs, 8 LDS.64, two chains
__device__ __forceinline__ void gemm8(float d[4], const unsigned* bank, int nt, int lane,
                                      const unsigned (&A)[8][4]) {
  const uint2* bk = reinterpret_cast<const uint2*>(bank) + (nt * 8) * 32 + lane;
  float e[4] = {0.f, 0.f, 0.f, 0.f};
#pragma unroll
  for (int kf = 0; kf < 8; kf += 2) {
    uint2 b0 = bk[kf * 32];
    uint2 b1 = bk[(kf + 1) * 32];
    mma_tf32(d, A[kf], b0);
    mma_tf32(e, A[kf + 1], b1);
  }
#pragma unroll
  for (int j = 0; j < 4; j++) d[j] += e[j];
}

// bf16 K=64 gemm: 4 MMAs, 4 LDS.64, two chains
__device__ __forceinline__ void gemm4_16(float d[4], const unsigned* bank, int nt, int lane,
                                         const unsigned (&A16)[4][4]) {
  const uint2* bk = reinterpret_cast<const uint2*>(bank) + (nt * 4) * 32 + lane;
  float e[4] = {0.f, 0.f, 0.f, 0.f};
  uint2 b0 = bk[0 * 32], b1 = bk[1 * 32], b2 = bk[2 * 32], b3 = bk[3 * 32];
  mma_bf16(d, A16[0], b0);
  mma_bf16(e, A16[1], b1);
  mma_bf16(d, A16[2], b2);
  mma_bf16(e, A16[3], b3);
#pragma unroll
  for (int j = 0; j < 4; j++) d[j] += e[j];
}

// D-layout quad -> tf32 A-layout frag for kf=nt
__device__ __forceinline__ void d2a_one(unsigned (&Akf)[4], const float v[4], int lane) {
  const int c = lane & 3;
  const int base = lane & ~3;
  const int s1 = base | (c >> 1);
  const int s2 = s1 + 2;
  const bool odd = (c & 1);
  float v0a = __shfl_sync(0xffffffffu, v[0], s1);
  float v1a = __shfl_sync(0xffffffffu, v[1], s1);
  float v2a = __shfl_sync(0xffffffffu, v[2], s1);
  float v3a = __shfl_sync(0xffffffffu, v[3], s1);
  float v0b = __shfl_sync(0xffffffffu, v[0], s2);
  float v1b = __shfl_sync(0xffffffffu, v[1], s2);
  float v2b = __shfl_sync(0xffffffffu, v[2], s2);
  float v3b = __shfl_sync(0xffffffffu, v[3], s2);
  Akf[0] = cvt_tf32(odd ? v1a : v0a);
  Akf[1] = cvt_tf32(odd ? v3a : v2a);
  Akf[2] = cvt_tf32(odd ? v1b : v0b);
  Akf[3] = cvt_tf32(odd ? v3b : v2b);
}

// hD (D layout) -> bf16 A16 frags (R6 identity: no shuffles)
__device__ __forceinline__ void build_a16(unsigned (&A16)[4][4], const float (&hD)[8][4]) {
#pragma unroll
  for (int nt = 0; nt < 8; nt++) {
    int kf = nt >> 1, r0 = (nt & 1) * 2;
    A16[kf][r0]     = packbf(hD[nt][0], hD[nt][1]);
    A16[kf][r0 + 1] = packbf(hD[nt][2], hD[nt][3]);
  }
}

// fill tf32 B-fragment bank (LDS.64 layout) from W[n][128] cols koff..+63
__device__ __forceinline__ void fill_frag(unsigned* dst, const float* __restrict__ W,
                                          int koff, int ntn, int tid) {
  int total = ntn * 8 * 32 * 2;
  for (int i = tid; i < total; i += NTHREADS) {
    int w = i & 1;
    int lane = (i >> 1) & 31;
    int kf = (i >> 6) & 7;
    int nt = i >> 9;
    int n = nt * 8 + (lane >> 2);
    int k = kf * 8 + (lane & 3) + w * 4;
    dst[i] = cvt_tf32(W[n * 128 + koff + k]);
  }
}

// fill bf16 k16 B-fragment bank from W[n][128] cols koff..+63
__device__ __forceinline__ void fill_frag16(unsigned* dst, const float* __restrict__ W,
                                            int koff, int ntn, int tid) {
  int total = ntn * 4 * 32;   // uint2 entries
  uint2* d2 = reinterpret_cast<uint2*>(dst);
  for (int i = tid; i < total; i += NTHREADS) {
    int lane = i & 31;
    int kf = (i >> 5) & 3;
    int nt = i >> 7;
    int n = nt * 8 + (lane >> 2);
    int kb = koff + kf * 16 + (lane & 3) * 2;
    uint2 v;
    v.x = packbf(W[n * 128 + kb],     W[n * 128 + kb + 1]);
    v.y = packbf(W[n * 128 + kb + 8], W[n * 128 + kb + 9]);
    d2[i] = v;
  }
}

__device__ __forceinline__ void build_xa(
    unsigned (&XA)[8][4], const float* __restrict__ pf, int pA, int pB, int c) {
  const float* xA = pf + (size_t)pA * 64;
  const float* xB = pf + (size_t)pB * 64;
#pragma unroll
  for (int kf = 0; kf < 8; kf++) {
    XA[kf][0] = cvt_tf32(__ldg(xA + kf * 8 + c));
    XA[kf][1] = cvt_tf32(__ldg(xB + kf * 8 + c));
    XA[kf][2] = cvt_tf32(__ldg(xA + kf * 8 + c + 4));
    XA[kf][3] = cvt_tf32(__ldg(xB + kf * 8 + c + 4));
  }
}

// bf16 x A16 frags
__device__ __forceinline__ void build_xa16(
    unsigned (&XA16)[4][4], const float* __restrict__ pf, int pA, int pB, int c) {
  const float2* xA = reinterpret_cast<const float2*>(pf + (size_t)pA * 64);
  const float2* xB = reinterpret_cast<const float2*>(pf + (size_t)pB * 64);
#pragma unroll
  for (int kf = 0; kf < 4; kf++) {
    float2 a0 = __ldg(xA + kf * 8 + c);
    float2 b0 = __ldg(xB + kf * 8 + c);
    float2 a1 = __ldg(xA + kf * 8 + c + 4);
    float2 b1 = __ldg(xB + kf * 8 + c + 4);
    XA16[kf][0] = packbf(a0.x, a0.y);
    XA16[kf][1] = packbf(b0.x, b0.y);
    XA16[kf][2] = packbf(a1.x, a1.y);
    XA16[kf][3] = packbf(b1.x, b1.y);
  }
}

__global__ __launch_bounds__(NTHREADS, 1)
void gru_mix16_kernel(
    const float* __restrict__ before, const float* __restrict__ after,
    const float* __restrict__ pf, const int* __restrict__ coords,
    const float* __restrict__ Wz, const float* __restrict__ bz,
    const float* __restrict__ Wr, const float* __restrict__ br,
    const float* __restrict__ Wq, const float* __restrict__ bq,
    const float* __restrict__ Wd1, const float* __restrict__ bd1,
    const float* __restrict__ Wd2, const float* __restrict__ bd2,
    float* __restrict__ out, int N, int total_pts)
{
  extern __shared__ char smem_raw[];
  Smem& s = *reinterpret_cast<Smem*>(smem_raw);
  const int tid = threadIdx.x;
  const int wid = tid >> 5, lane = tid & 31;
  const int g = lane >> 2, c = lane & 3;

  // ---- one-time weight fragment prep ----
  fill_frag16(s.wz_h16, Wz, 0, 8, tid);
  fill_frag16(s.wr_h16, Wr, 0, 8, tid);
  fill_frag16(s.wz_x16, Wz, 64, 8, tid);
  fill_frag16(s.wr_x16, Wr, 64, 8, tid);
  fill_frag(s.wq_h, Wq, 0, 8, tid);
  fill_frag(s.wq_x, Wq, 64, 8, tid);
  fill_frag(s.wd_h, Wd1, 0, 4, tid);
  fill_frag(s.wd_x, Wd1, 64, 4, tid);
  if (tid < 64) { s.bz[tid] = bz[tid]; s.br[tid] = br[tid]; s.bq[tid] = bq[tid]; }
  if (tid < 32) s.bd1[tid] = bd1[tid];
  if (tid < 96) s.Wd2[tid] = Wd2[tid];
  if (tid < 3)  s.bd2[tid] = bd2[tid];
  __syncthreads();

  const int ntiles = (total_pts + TILE_M - 1) / TILE_M;

  for (int tile = blockIdx.x; tile < ntiles; tile += gridDim.x) {
    const int ptA = tile * TILE_M + wid * 16 + g;   // rows 0-7
    const int ptB = ptA + 8;                         // rows 8-15
    const bool vA = ptA < total_pts, vB = ptB < total_pts;
    const int last = total_pts - 1;
    const int pA = vA ? ptA : last, pB = vB ? ptB : last;

    // ---- gather h in D layout ----
    float hD[8][4];
    {
      const int* ccA = coords + (size_t)pA * 3;
      const int* ccB = coords + (size_t)pB * 3;
      int spA = ccA[0] * I_STRIDE + ccA[1] * J_STRIDE + ccA[2];
      int spB = ccB[0] * I_STRIDE + ccB[1] * J_STRIDE + ccB[2];
      const float* befA = before + (size_t)(pA / N) * B_STRIDE + (unsigned)spA;
      const float* aftA = after  + (size_t)(pA / N) * B_STRIDE + (unsigned)spA;
      const float* befB = before + (size_t)(pB / N) * B_STRIDE + (unsigned)spB;
      const float* aftB = after  + (size_t)(pB / N) * B_STRIDE + (unsigned)spB;
#pragma unroll
      for (int nt = 0; nt < 8; nt++) {
        int cb = (nt & 3) * 8 + 2 * c;
        const float* pa = (nt < 4) ? befA : aftA;
        const float* pb = (nt < 4) ? befB : aftB;
        hD[nt][0] = __ldg(pa + (size_t)cb * C_STRIDE);
        hD[nt][1] = __ldg(pa + (size_t)(cb + 1) * C_STRIDE);
        hD[nt][2] = __ldg(pb + (size_t)cb * C_STRIDE);
        hD[nt][3] = __ldg(pb + (size_t)(cb + 1) * C_STRIDE);
      }
    }

    // ---- x-projection GEMMs -> fp16 smem dumps (z,r bf16; q,dec tf32) ----
    {
      unsigned XA16[4][4];
      build_xa16(XA16, pf, pA, pB, c);
#pragma unroll
      for (int nt = 0; nt < 8; nt++) {
        int n0 = nt * 8 + 2 * c;
        float d[4];
        d[0] = s.bz[n0]; d[1] = s.bz[n0 + 1]; d[2] = d[0]; d[3] = d[1];
        gemm4_16(d, s.wz_x16, nt, lane, XA16);
        xp_store(&s.xp[wid][nt][lane][0], d);
      }
#pragma unroll
      for (int nt = 0; nt < 8; nt++) {
        int n0 = nt * 8 + 2 * c;
        float d[4];
        d[0] = s.br[n0]; d[1] = s.br[n0 + 1]; d[2] = d[0]; d[3] = d[1];
        gemm4_16(d, s.wr_x16, nt, lane, XA16);
        xp_store(&s.xp[wid][8 + nt][lane][0], d);
      }
    }
    {
      unsigned XA[8][4];
      build_xa(XA, pf, pA, pB, c);
#pragma unroll
      for (int nt = 0; nt < 8; nt++) {
        int n0 = nt * 8 + 2 * c;
        float d[4];
        d[0] = s.bq[n0]; d[1] = s.bq[n0 + 1]; d[2] = d[0]; d[3] = d[1];
        gemm8(d, s.wq_x, nt, lane, XA);
        xp_store(&s.xp[wid][16 + nt][lane][0], d);
      }
#pragma unroll
      for (int nt = 0; nt < 4; nt++) {
        int n0 = nt * 8 + 2 * c;
        float d[4];
        d[0] = s.bd1[n0]; d[1] = s.bd1[n0 + 1]; d[2] = d[0]; d[3] = d[1];
        gemm8(d, s.wd_x, nt, lane, XA);
        xp_store(&s.xp[wid][24 + nt][lane][0], d);
      }
    }

    // ---- 4 GRU iterations ----
#pragma unroll 1
    for (int it = 0; it < 4; it++) {
      unsigned A16[4][4];
      build_a16(A16, hD);          // bf16 h frags (no shuffles)
      unsigned R[8][4];
      // pass 1: r gate (bf16, reads A16) -> R = tf32(r*h) in A layout
#pragma unroll
      for (int nt = 0; nt < 8; nt++) {
        float dr[4];
        xp_load(dr, &s.xp[wid][8 + nt][lane][0]);
        gemm4_16(dr, s.wr_h16, nt, lane, A16);
        float rh[4];
#pragma unroll
        for (int j = 0; j < 4; j++) rh[j] = sigm(dr[j]) * hD[nt][j];
        d2a_one(R[nt], rh, lane);
      }
      // pass 2: z gate (bf16, reads A16) + q gate (tf32, reads R); update hD
#pragma unroll
      for (int nt = 0; nt < 8; nt++) {
        float dz[4], dq[4];
        xp_load(dz, &s.xp[wid][nt][lane][0]);
        gemm4_16(dz, s.wz_h16, nt, lane, A16);
        xp_load(dq, &s.xp[wid][16 + nt][lane][0]);
        gemm8(dq, s.wq_h, nt, lane, R);
#pragma unroll
        for (int j = 0; j < 4; j++)
          hD[nt][j] = fmaf(sigm(dz[j]), tanh_hw(dq[j]) - hD[nt][j], hD[nt][j]);
      }
    }

    // ---- decoder: hmid = gelu(Wd1h@h + dec_xp) (tf32) ----
    float hm[4][4];
    {
      unsigned Atf[8][4];
#pragma unroll
      for (int nt = 0; nt < 8; nt++) d2a_one(Atf[nt], hD[nt], lane);
#pragma unroll
      for (int nt = 0; nt < 4; nt++) {
        float d[4];
        xp_load(d, &s.xp[wid][24 + nt][lane][0]);
        gemm8(d, s.wd_h, nt, lane, Atf);
#pragma unroll
        for (int j = 0; j < 4; j++)
          hm[nt][j] = 0.5f * d[j] * (1.0f + erff(d[j] * 0.70710678118654752f));
      }
    }

    // ---- flow = Wd2 @ hmid + bd2, quad reduction ----
    float fA[3] = {0.f, 0.f, 0.f}, fB[3] = {0.f, 0.f, 0.f};
#pragma unroll
    for (int nt = 0; nt < 4; nt++) {
      int n0 = nt * 8 + 2 * c;
#pragma unroll
      for (int o = 0; o < 3; o++) {
        float w0 = s.Wd2[o * 32 + n0], w1 = s.Wd2[o * 32 + n0 + 1];
        fA[o] += w0 * hm[nt][0] + w1 * hm[nt][1];
        fB[o] += w0 * hm[nt][2] + w1 * hm[nt][3];
      }
    }
#pragma unroll
    for (int o = 0; o < 3; o++) {
      fA[o] += __shfl_xor_sync(0xffffffffu, fA[o], 1);
      fA[o] += __shfl_xor_sync(0xffffffffu, fA[o], 2);
      fB[o] += __shfl_xor_sync(0xffffffffu, fB[o], 1);
      fB[o] += __shfl_xor_sync(0xffffffffu, fB[o], 2);
    }
    if (c < 3) {
      if (vA) out[(size_t)ptA * 3 + c] = fA[c] + s.bd2[c];
      if (vB) out[(size_t)ptB * 3 + c] = fB[c] + s.bd2[c];
    }
  }
}

extern "C" void kernel_launch(void* const* d_in, const int* in_sizes, int n_in,
                              void* d_out, int out_size) {
  const float* before = (const float*)d_in[0];
  const float* after  = (const float*)d_in[1];
  const float* pf     = (const float*)d_in[2];
  const int*   coords = (const int*)d_in[3];     // int32
  const float* Wz  = (const float*)d_in[4];
  const float* bz  = (const float*)d_in[5];
  const float* Wr  = (const float*)d_in[6];
  const float* br  = (const float*)d_in[7];
  const float* Wq  = (const float*)d_in[8];
  const float* bq  = (const float*)d_in[9];
  const float* Wd1 = (const float*)d_in[10];
  const float* bd1 = (const float*)d_in[11];
  const float* Wd2 = (const float*)d_in[12];
  const float* bd2 = (const float*)d_in[13];
  float* out = (float*)d_out;

  int B = in_sizes[0] / (int)(32u * 256u * 256u * 32u);
  if (B < 1) B = 1;
  int total_pts = in_sizes[3] / 3;
  int N = total_pts / B;

  cudaFuncSetAttribute(gru_mix16_kernel,
                       cudaFuncAttributeMaxDynamicSharedMemorySize,
                       (int)sizeof(Smem));

  gru_mix16_kernel<<<152, NTHREADS, sizeof(Smem)>>>(
      before, after, pf, coords, Wz, bz, Wr, br, Wq, bq,
      Wd1, bd1, Wd2, bd2, out, N, total_pts);
}

// round 15
// speedup vs baseline: 1.0508x; 1.0508x over previous
#include <cuda_runtime.h>
#include <cuda_fp16.h>
#include <math.h>
#include <stdint.h>

#define NTHREADS 448
#define NWARPS 14
#define TILE_M 224     // 14 warps x 16 points

// fixed problem geometry
#define C_STRIDE 2097152ULL     // 256*256*32
#define B_STRIDE 67108864ULL    // 32*256*256*32
#define I_STRIDE 8192
#define J_STRIDE 32

struct __align__(16) Smem {
  // bf16 k16 banks (z, r): uint2 per (nt,kf4,lane) -> 8KB each
  unsigned wz_h16[2048];
  unsigned wr_h16[2048];
  unsigned wz_x16[2048];
  unsigned wr_x16[2048];
  // tf32 k8 banks (q, dec): uint2 per (nt,kf8,lane)
  unsigned wq_h[4096];   // 16KB
  unsigned wq_x[4096];
  unsigned wd_h[2048];   // 8KB
  unsigned wd_x[2048];
  // xproj fp16x2: [warp][entry 0-27 (z0-7,r8-15,q16-23,dec24-27)][lane][2]
  unsigned xp[NWARPS][28][32][2];
  float bz[64], br[64], bq[64], bd1[32];
  float Wd2[96], bd2[4];
};

__device__ __forceinline__ float tanh_hw(float x) {
  float y;
  asm("tanh.approx.f32 %0, %1;" : "=f"(y) : "f"(x));
  return y;
}
__device__ __forceinline__ float sigm(float x) {
  return fmaf(0.5f, tanh_hw(0.5f * x), 0.5f);
}
// fast gelu (tanh form, HW tanh)
__device__ __forceinline__ float gelu_fast(float x) {
  float t = tanh_hw(0.7978845608f * fmaf(0.044715f, x * x * x, x));
  return 0.5f * x * (1.0f + t);
}
__device__ __forceinline__ unsigned cvt_tf32(float f) {
  unsigned u;
  asm("cvt.rna.tf32.f32 %0, %1;" : "=r"(u) : "f"(f));
  return u;
}
// pack two floats -> bf16x2 (lo in low half)
__device__ __forceinline__ unsigned packbf(float lo_, float hi_) {
  unsigned r;
  asm("cvt.rn.bf16x2.f32 %0, %1, %2;" : "=r"(r) : "f"(hi_), "f"(lo_));
  return r;
}

// ---- fp16 xp store/load ----
__device__ __forceinline__ void xp_store(unsigned* dst, const float d[4]) {
  __half2 a = __floats2half2_rn(d[0], d[1]);
  __half2 b = __floats2half2_rn(d[2], d[3]);
  dst[0] = *reinterpret_cast<unsigned*>(&a);
  dst[1] = *reinterpret_cast<unsigned*>(&b);
}
__device__ __forceinline__ void xp_load(float d[4], const unsigned* src) {
  uint2 v = *reinterpret_cast<const uint2*>(src);
  __half2 a = *reinterpret_cast<__half2*>(&v.x);
  __half2 b = *reinterpret_cast<__half2*>(&v.y);
  float2 fa = __half22float2(a), fb = __half22float2(b);
  d[0] = fa.x; d[1] = fa.y; d[2] = fb.x; d[3] = fb.y;
}

// m16n8k8 tf32 MMA
__device__ __forceinline__ void mma_tf32(float d[4], const unsigned a[4], uint2 b) {
  asm volatile(
    "mma.sync.aligned.m16n8k8.row.col.f32.tf32.tf32.f32 "
    "{%0,%1,%2,%3}, {%4,%5,%6,%7}, {%8,%9}, {%0,%1,%2,%3};"
    : "+f"(d[0]), "+f"(d[1]), "+f"(d[2]), "+f"(d[3])
    : "r"(a[0]), "r"(a[1]), "r"(a[2]), "r"(a[3]), "r"(b.x), "r"(b.y));
}
// m16n8k16 bf16 MMA
__device__ __forceinline__ void mma_bf16(float d[4], const unsigned a[4], uint2 b) {
  asm volatile(
    "mma.sync.aligned.m16n8k16.row.col.f32.bf16.bf16.f32 "
    "{%0,%1,%2,%3}, {%4,%5,%6,%7}, {%8,%9}, {%0,%1,%2,%3};"
    : "+f"(d[0]), "+f"(d[1]), "+f"(d[2]), "+f"(d[3])
    : "r"(a[0]), "r"(a[1]), "r"(a[2]), "r"(a[3]), "r"(b.x), "r"(b.y));
}

// tf32 K=64 gemm from zero: 8 MMAs, 8 LDS.64, two chains
__device__ __forceinline__ void gemm8z(float d[4], const unsigned* bank, int nt, int lane,
                                       const unsigned (&A)[8][4]) {
  const uint2* bk = reinterpret_cast<const uint2*>(bank) + (nt * 8) * 32 + lane;
  float e[4] = {0.f, 0.f, 0.f, 0.f};
  d[0] = d[1] = d[2] = d[3] = 0.f;
#pragma unroll
  for (int kf = 0; kf < 8; kf += 2) {
    uint2 b0 = bk[kf * 32];
    uint2 b1 = bk[(kf + 1) * 32];
    mma_tf32(d, A[kf], b0);
    mma_tf32(e, A[kf + 1], b1);
  }
#pragma unroll
  for (int j = 0; j < 4; j++) d[j] += e[j];
}

// bf16 K=64 gemm from zero: 4 MMAs, 4 LDS.64, two chains
__device__ __forceinline__ void gemm4z(float d[4], const unsigned* bank, int nt, int lane,
                                       const unsigned (&A16)[4][4]) {
  const uint2* bk = reinterpret_cast<const uint2*>(bank) + (nt * 4) * 32 + lane;
  float e[4] = {0.f, 0.f, 0.f, 0.f};
  d[0] = d[1] = d[2] = d[3] = 0.f;
  uint2 b0 = bk[0 * 32], b1 = bk[1 * 32], b2 = bk[2 * 32], b3 = bk[3 * 32];
  mma_bf16(d, A16[0], b0);
  mma_bf16(e, A16[1], b1);
  mma_bf16(d, A16[2], b2);
  mma_bf16(e, A16[3], b3);
#pragma unroll
  for (int j = 0; j < 4; j++) d[j] += e[j];
}

// D-layout quad -> tf32 A-layout frag for kf=nt
__device__ __forceinline__ void d2a_one(unsigned (&Akf)[4], const float v[4], int lane) {
  const int c = lane & 3;
  const int base = lane & ~3;
  const int s1 = base | (c >> 1);
  const int s2 = s1 + 2;
  const bool odd = (c & 1);
  float v0a = __shfl_sync(0xffffffffu, v[0], s1);
  float v1a = __shfl_sync(0xffffffffu, v[1], s1);
  float v2a = __shfl_sync(0xffffffffu, v[2], s1);
  float v3a = __shfl_sync(0xffffffffu, v[3], s1);
  float v0b = __shfl_sync(0xffffffffu, v[0], s2);
  float v1b = __shfl_sync(0xffffffffu, v[1], s2);
  float v2b = __shfl_sync(0xffffffffu, v[2], s2);
  float v3b = __shfl_sync(0xffffffffu, v[3], s2);
  Akf[0] = cvt_tf32(odd ? v1a : v0a);
  Akf[1] = cvt_tf32(odd ? v3a : v2a);
  Akf[2] = cvt_tf32(odd ? v1b : v0b);
  Akf[3] = cvt_tf32(odd ? v3b : v2b);
}

// hD (D layout) -> bf16 A16 frags (R6 identity: no shuffles)
__device__ __forceinline__ void build_a16(unsigned (&A16)[4][4], const float (&hD)[8][4]) {
#pragma unroll
  for (int nt = 0; nt < 8; nt++) {
    int kf = nt >> 1, r0 = (nt & 1) * 2;
    A16[kf][r0]     = packbf(hD[nt][0], hD[nt][1]);
    A16[kf][r0 + 1] = packbf(hD[nt][2], hD[nt][3]);
  }
}

// fill tf32 B-fragment bank (LDS.64 layout) from W[n][128] cols koff..+63
__device__ __forceinline__ void fill_frag(unsigned* dst, const float* __restrict__ W,
                                          int koff, int ntn, int tid) {
  int total = ntn * 8 * 32 * 2;
  for (int i = tid; i < total; i += NTHREADS) {
    int w = i & 1;
    int lane = (i >> 1) & 31;
    int kf = (i >> 6) & 7;
    int nt = i >> 9;
    int n = nt * 8 + (lane >> 2);
    int k = kf * 8 + (lane & 3) + w * 4;
    dst[i] = cvt_tf32(W[n * 128 + koff + k]);
  }
}

// fill bf16 k16 B-fragment bank from W[n][128] cols koff..+63
__device__ __forceinline__ void fill_frag16(unsigned* dst, const float* __restrict__ W,
                                            int koff, int ntn, int tid) {
  int total = ntn * 4 * 32;   // uint2 entries
  uint2* d2 = reinterpret_cast<uint2*>(dst);
  for (int i = tid; i < total; i += NTHREADS) {
    int lane = i & 31;
    int kf = (i >> 5) & 3;
    int nt = i >> 7;
    int n = nt * 8 + (lane >> 2);
    int kb = koff + kf * 16 + (lane & 3) * 2;
    uint2 v;
    v.x = packbf(W[n * 128 + kb],     W[n * 128 + kb + 1]);
    v.y = packbf(W[n * 128 + kb + 8], W[n * 128 + kb + 9]);
    d2[i] = v;
  }
}

__device__ __forceinline__ void build_xa(
    unsigned (&XA)[8][4], const float* __restrict__ pf, int pA, int pB, int c) {
  const float* xA = pf + (size_t)pA * 64;
  const float* xB = pf + (size_t)pB * 64;
#pragma unroll
  for (int kf = 0; kf < 8; kf++) {
    XA[kf][0] = cvt_tf32(__ldg(xA + kf * 8 + c));
    XA[kf][1] = cvt_tf32(__ldg(xB + kf * 8 + c));
    XA[kf][2] = cvt_tf32(__ldg(xA + kf * 8 + c + 4));
    XA[kf][3] = cvt_tf32(__ldg(xB + kf * 8 + c + 4));
  }
}

// bf16 x A16 frags
__device__ __forceinline__ void build_xa16(
    unsigned (&XA16)[4][4], const float* __restrict__ pf, int pA, int pB, int c) {
  const float2* xA = reinterpret_cast<const float2*>(pf + (size_t)pA * 64);
  const float2* xB = reinterpret_cast<const float2*>(pf + (size_t)pB * 64);
#pragma unroll
  for (int kf = 0; kf < 4; kf++) {
    float2 a0 = __ldg(xA + kf * 8 + c);
    float2 b0 = __ldg(xB + kf * 8 + c);
    float2 a1 = __ldg(xA + kf * 8 + c + 4);
    float2 b1 = __ldg(xB + kf * 8 + c + 4);
    XA16[kf][0] = packbf(a0.x, a0.y);
    XA16[kf][1] = packbf(b0.x, b0.y);
    XA16[kf][2] = packbf(a1.x, a1.y);
    XA16[kf][3] = packbf(b1.x, b1.y);
  }
}

__global__ __launch_bounds__(NTHREADS, 1)
void gru_mix15_kernel(
    const float* __restrict__ before, const float* __restrict__ after,
    const float* __restrict__ pf, const int* __restrict__ coords,
    const float* __restrict__ Wz, const float* __restrict__ bz,
    const float* __restrict__ Wr, const float* __restrict__ br,
    const float* __restrict__ Wq, const float* __restrict__ bq,
    const float* __restrict__ Wd1, const float* __restrict__ bd1,
    const float* __restrict__ Wd2, const float* __restrict__ bd2,
    float* __restrict__ out, int N, int total_pts)
{
  extern __shared__ char smem_raw[];
  Smem& s = *reinterpret_cast<Smem*>(smem_raw);
  const int tid = threadIdx.x;
  const int wid = tid >> 5, lane = tid & 31;
  const int g = lane >> 2, c = lane & 3;

  // ---- one-time weight fragment prep ----
  fill_frag16(s.wz_h16, Wz, 0, 8, tid);
  fill_frag16(s.wr_h16, Wr, 0, 8, tid);
  fill_frag16(s.wz_x16, Wz, 64, 8, tid);
  fill_frag16(s.wr_x16, Wr, 64, 8, tid);
  fill_frag(s.wq_h, Wq, 0, 8, tid);
  fill_frag(s.wq_x, Wq, 64, 8, tid);
  fill_frag(s.wd_h, Wd1, 0, 4, tid);
  fill_frag(s.wd_x, Wd1, 64, 4, tid);
  if (tid < 64) { s.bz[tid] = bz[tid]; s.br[tid] = br[tid]; s.bq[tid] = bq[tid]; }
  if (tid < 32) s.bd1[tid] = bd1[tid];
  if (tid < 96) s.Wd2[tid] = Wd2[tid];
  if (tid < 3)  s.bd2[tid] = bd2[tid];
  __syncthreads();

  const int ntiles = (total_pts + TILE_M - 1) / TILE_M;

  for (int tile = blockIdx.x; tile < ntiles; tile += gridDim.x) {
    const int ptA = tile * TILE_M + wid * 16 + g;   // rows 0-7
    const int ptB = ptA + 8;                         // rows 8-15
    const bool vA = ptA < total_pts, vB = ptB < total_pts;
    const int last = total_pts - 1;
    const int pA = vA ? ptA : last, pB = vB ? ptB : last;

    // ---- gather h in D layout ----
    float hD[8][4];
    {
      const int* ccA = coords + (size_t)pA * 3;
      const int* ccB = coords + (size_t)pB * 3;
      int spA = ccA[0] * I_STRIDE + ccA[1] * J_STRIDE + ccA[2];
      int spB = ccB[0] * I_STRIDE + ccB[1] * J_STRIDE + ccB[2];
      const float* befA = before + (size_t)(pA / N) * B_STRIDE + (unsigned)spA;
      const float* aftA = after  + (size_t)(pA / N) * B_STRIDE + (unsigned)spA;
      const float* befB = before + (size_t)(pB / N) * B_STRIDE + (unsigned)spB;
      const float* aftB = after  + (size_t)(pB / N) * B_STRIDE + (unsigned)spB;
#pragma unroll
      for (int nt = 0; nt < 8; nt++) {
        int cb = (nt & 3) * 8 + 2 * c;
        const float* pa = (nt < 4) ? befA : aftA;
        const float* pb = (nt < 4) ? befB : aftB;
        hD[nt][0] = __ldg(pa + (size_t)cb * C_STRIDE);
        hD[nt][1] = __ldg(pa + (size_t)(cb + 1) * C_STRIDE);
        hD[nt][2] = __ldg(pb + (size_t)cb * C_STRIDE);
        hD[nt][3] = __ldg(pb + (size_t)(cb + 1) * C_STRIDE);
      }
    }

    // ---- x-projection GEMMs -> fp16 smem dumps (z,r bf16; q,dec tf32) ----
    // biases folded into xp here so iteration gemms can start from zero
    {
      unsigned XA16[4][4];
      build_xa16(XA16, pf, pA, pB, c);
#pragma unroll
      for (int nt = 0; nt < 8; nt++) {
        int n0 = nt * 8 + 2 * c;
        float d[4];
        gemm4z(d, s.wz_x16, nt, lane, XA16);
        d[0] += s.bz[n0]; d[1] += s.bz[n0 + 1]; d[2] += s.bz[n0]; d[3] += s.bz[n0 + 1];
        xp_store(&s.xp[wid][nt][lane][0], d);
      }
#pragma unroll
      for (int nt = 0; nt < 8; nt++) {
        int n0 = nt * 8 + 2 * c;
        float d[4];
        gemm4z(d, s.wr_x16, nt, lane, XA16);
        d[0] += s.br[n0]; d[1] += s.br[n0 + 1]; d[2] += s.br[n0]; d[3] += s.br[n0 + 1];
        xp_store(&s.xp[wid][8 + nt][lane][0], d);
      }
    }
    {
      unsigned XA[8][4];
      build_xa(XA, pf, pA, pB, c);
#pragma unroll
      for (int nt = 0; nt < 8; nt++) {
        int n0 = nt * 8 + 2 * c;
        float d[4];
        gemm8z(d, s.wq_x, nt, lane, XA);
        d[0] += s.bq[n0]; d[1] += s.bq[n0 + 1]; d[2] += s.bq[n0]; d[3] += s.bq[n0 + 1];
        xp_store(&s.xp[wid][16 + nt][lane][0], d);
      }
#pragma unroll
      for (int nt = 0; nt < 4; nt++) {
        int n0 = nt * 8 + 2 * c;
        float d[4];
        gemm8z(d, s.wd_x, nt, lane, XA);
        d[0] += s.bd1[n0]; d[1] += s.bd1[n0 + 1]; d[2] += s.bd1[n0]; d[3] += s.bd1[n0 + 1];
        xp_store(&s.xp[wid][24 + nt][lane][0], d);
      }
    }

    // ---- 4 GRU iterations ----
#pragma unroll 1
    for (int it = 0; it < 4; it++) {
      unsigned A16[4][4];
      build_a16(A16, hD);          // bf16 h frags (no shuffles)
      unsigned R[8][4];
      // pass 1: r gate (bf16, reads A16) -> R = tf32(r*h) in A layout
#pragma unroll
      for (int nt = 0; nt < 8; nt++) {
        float dr[4], xr[4];
        gemm4z(dr, s.wr_h16, nt, lane, A16);
        xp_load(xr, &s.xp[wid][8 + nt][lane][0]);
        float rh[4];
#pragma unroll
        for (int j = 0; j < 4; j++) rh[j] = sigm(dr[j] + xr[j]) * hD[nt][j];
        d2a_one(R[nt], rh, lane);
      }
      // pass 2: z gate (bf16, reads A16) + q gate (tf32, reads R); update hD
#pragma unroll
      for (int nt = 0; nt < 8; nt++) {
        float dz[4], dq[4], xz[4], xq[4];
        gemm4z(dz, s.wz_h16, nt, lane, A16);
        gemm8z(dq, s.wq_h, nt, lane, R);
        xp_load(xz, &s.xp[wid][nt][lane][0]);
        xp_load(xq, &s.xp[wid][16 + nt][lane][0]);
#pragma unroll
        for (int j = 0; j < 4; j++)
          hD[nt][j] = fmaf(sigm(dz[j] + xz[j]), tanh_hw(dq[j] + xq[j]) - hD[nt][j], hD[nt][j]);
      }
    }

    // ---- decoder: hmid = gelu(Wd1h@h + dec_xp) (tf32, fast gelu) ----
    float hm[4][4];
    {
      unsigned Atf[8][4];
#pragma unroll
      for (int nt = 0; nt < 8; nt++) d2a_one(Atf[nt], hD[nt], lane);
#pragma unroll
      for (int nt = 0; nt < 4; nt++) {
        float d[4], xd[4];
        gemm8z(d, s.wd_h, nt, lane, Atf);
        xp_load(xd, &s.xp[wid][24 + nt][lane][0]);
#pragma unroll
        for (int j = 0; j < 4; j++)
          hm[nt][j] = gelu_fast(d[j] + xd[j]);
      }
    }

    // ---- flow = Wd2 @ hmid + bd2, quad reduction ----
    float fA[3] = {0.f, 0.f, 0.f}, fB[3] = {0.f, 0.f, 0.f};
#pragma unroll
    for (int nt = 0; nt < 4; nt++) {
      int n0 = nt * 8 + 2 * c;
#pragma unroll
      for (int o = 0; o < 3; o++) {
        float w0 = s.Wd2[o * 32 + n0], w1 = s.Wd2[o * 32 + n0 + 1];
        fA[o] += w0 * hm[nt][0] + w1 * hm[nt][1];
        fB[o] += w0 * hm[nt][2] + w1 * hm[nt][3];
      }
    }
#pragma unroll
    for (int o = 0; o < 3; o++) {
      fA[o] += __shfl_xor_sync(0xffffffffu, fA[o], 1);
      fA[o] += __shfl_xor_sync(0xffffffffu, fA[o], 2);
      fB[o] += __shfl_xor_sync(0xffffffffu, fB[o], 1);
      fB[o] += __shfl_xor_sync(0xffffffffu, fB[o], 2);
    }
    if (c < 3) {
      if (vA) out[(size_t)ptA * 3 + c] = fA[c] + s.bd2[c];
      if (vB) out[(size_t)ptB * 3 + c] = fB[c] + s.bd2[c];
    }
  }
}

extern "C" void kernel_launch(void* const* d_in, const int* in_sizes, int n_in,
                              void* d_out, int out_size) {
  const float* before = (const float*)d_in[0];
  const float* after  = (const float*)d_in[1];
  const float* pf     = (const float*)d_in[2];
  const int*   coords = (const int*)d_in[3];     // int32
  const float* Wz  = (const float*)d_in[4];
  const float* bz  = (const float*)d_in[5];
  const float* Wr  = (const float*)d_in[6];
  const float* br  = (const float*)d_in[7];
  const float* Wq  = (const float*)d_in[8];
  const float* bq  = (const float*)d_in[9];
  const float* Wd1 = (const float*)d_in[10];
  const float* bd1 = (const float*)d_in[11];
  const float* Wd2 = (const float*)d_in[12];
  const float* bd2 = (const float*)d_in[13];
  float* out = (float*)d_out;

  int B = in_sizes[0] / (int)(32u * 256u * 256u * 32u);
  if (B < 1) B = 1;
  int total_pts = in_sizes[3] / 3;
  int N = total_pts / B;

  cudaFuncSetAttribute(gru_mix15_kernel,
                       cudaFuncAttributeMaxDynamicSharedMemorySize,
                       (int)sizeof(Smem));

  gru_mix15_kernel<<<152, NTHREADS, sizeof(Smem)>>>(
      before, after, pf, coords, Wz, bz, Wr, br, Wq, bq,
      Wd1, bd1, Wd2, bd2, out, N, total_pts);
}

// round 17
// speedup vs baseline: 1.0522x; 1.0013x over previous
#include <cuda_runtime.h>
#include <cuda_fp16.h>
#include <math.h>
#include <stdint.h>

#define NTHREADS 448
#define NWARPS 14
#define TILE_M 224     // 14 warps x 16 points

// fixed problem geometry
#define C_STRIDE 2097152ULL     // 256*256*32
#define B_STRIDE 67108864ULL    // 32*256*256*32
#define I_STRIDE 8192
#define J_STRIDE 32

struct __align__(16) Smem {
  // bf16 k16 banks (z, r): uint2 per (nt,kf4,lane) -> 8KB each
  unsigned wz_h16[2048];
  unsigned wr_h16[2048];
  unsigned wz_x16[2048];
  unsigned wr_x16[2048];
  // tf32 k8 banks (q, dec): uint2 per (nt,kf8,lane)
  unsigned wq_h[4096];   // 16KB
  unsigned wq_x[4096];
  unsigned wd_h[2048];   // 8KB
  unsigned wd_x[2048];
  // xproj fp16x2: [warp][entry 0-27 (z0-7,r8-15,q16-23,dec24-27)][lane][2]
  unsigned xp[NWARPS][28][32][2];
  float bz[64], br[64], bq[64], bd1[32];
  float Wd2[96], bd2[4];
};

__device__ __forceinline__ float tanh_hw(float x) {
  float y;
  asm("tanh.approx.f32 %0, %1;" : "=f"(y) : "f"(x));
  return y;
}
__device__ __forceinline__ float sigm(float x) {
  return fmaf(0.5f, tanh_hw(0.5f * x), 0.5f);
}
// fast gelu (tanh form, HW tanh)
__device__ __forceinline__ float gelu_fast(float x) {
  float t = tanh_hw(0.7978845608f * fmaf(0.044715f, x * x * x, x));
  return 0.5f * x * (1.0f + t);
}
__device__ __forceinline__ unsigned cvt_tf32(float f) {
  unsigned u;
  asm("cvt.rna.tf32.f32 %0, %1;" : "=r"(u) : "f"(f));
  return u;
}
// pack two floats -> bf16x2 (lo in low half)
__device__ __forceinline__ unsigned packbf(float lo_, float hi_) {
  unsigned r;
  asm("cvt.rn.bf16x2.f32 %0, %1, %2;" : "=r"(r) : "f"(hi_), "f"(lo_));
  return r;
}

// ---- fp16 xp store/load ----
__device__ __forceinline__ void xp_store(unsigned* dst, const float d[4]) {
  __half2 a = __floats2half2_rn(d[0], d[1]);
  __half2 b = __floats2half2_rn(d[2], d[3]);
  dst[0] = *reinterpret_cast<unsigned*>(&a);
  dst[1] = *reinterpret_cast<unsigned*>(&b);
}
__device__ __forceinline__ void xp_load(float d[4], const unsigned* src) {
  uint2 v = *reinterpret_cast<const uint2*>(src);
  __half2 a = *reinterpret_cast<__half2*>(&v.x);
  __half2 b = *reinterpret_cast<__half2*>(&v.y);
  float2 fa = __half22float2(a), fb = __half22float2(b);
  d[0] = fa.x; d[1] = fa.y; d[2] = fb.x; d[3] = fb.y;
}

// m16n8k8 tf32 MMA
__device__ __forceinline__ void mma_tf32(float d[4], const unsigned a[4], uint2 b) {
  asm volatile(
    "mma.sync.aligned.m16n8k8.row.col.f32.tf32.tf32.f32 "
    "{%0,%1,%2,%3}, {%4,%5,%6,%7}, {%8,%9}, {%0,%1,%2,%3};"
    : "+f"(d[0]), "+f"(d[1]), "+f"(d[2]), "+f"(d[3])
    : "r"(a[0]), "r"(a[1]), "r"(a[2]), "r"(a[3]), "r"(b.x), "r"(b.y));
}
// m16n8k16 bf16 MMA
__device__ __forceinline__ void mma_bf16(float d[4], const unsigned a[4], uint2 b) {
  asm volatile(
    "mma.sync.aligned.m16n8k16.row.col.f32.bf16.bf16.f32 "
    "{%0,%1,%2,%3}, {%4,%5,%6,%7}, {%8,%9}, {%0,%1,%2,%3};"
    : "+f"(d[0]), "+f"(d[1]), "+f"(d[2]), "+f"(d[3])
    : "r"(a[0]), "r"(a[1]), "r"(a[2]), "r"(a[3]), "r"(b.x), "r"(b.y));
}

// tf32 K=64 gemm from zero: 8 MMAs, 8 LDS.64, two chains
__device__ __forceinline__ void gemm8z(float d[4], const unsigned* bank, int nt, int lane,
                                       const unsigned (&A)[8][4]) {
  const uint2* bk = reinterpret_cast<const uint2*>(bank) + (nt * 8) * 32 + lane;
  float e[4] = {0.f, 0.f, 0.f, 0.f};
  d[0] = d[1] = d[2] = d[3] = 0.f;
#pragma unroll
  for (int kf = 0; kf < 8; kf += 2) {
    uint2 b0 = bk[kf * 32];
    uint2 b1 = bk[(kf + 1) * 32];
    mma_tf32(d, A[kf], b0);
    mma_tf32(e, A[kf + 1], b1);
  }
#pragma unroll
  for (int j = 0; j < 4; j++) d[j] += e[j];
}

// bf16 K=64 gemm from zero: 4 MMAs, 4 LDS.64, two chains
__device__ __forceinline__ void gemm4z(float d[4], const unsigned* bank, int nt, int lane,
                                       const unsigned (&A16)[4][4]) {
  const uint2* bk = reinterpret_cast<const uint2*>(bank) + (nt * 4) * 32 + lane;
  float e[4] = {0.f, 0.f, 0.f, 0.f};
  d[0] = d[1] = d[2] = d[3] = 0.f;
  uint2 b0 = bk[0 * 32], b1 = bk[1 * 32], b2 = bk[2 * 32], b3 = bk[3 * 32];
  mma_bf16(d, A16[0], b0);
  mma_bf16(e, A16[1], b1);
  mma_bf16(d, A16[2], b2);
  mma_bf16(e, A16[3], b3);
#pragma unroll
  for (int j = 0; j < 4; j++) d[j] += e[j];
}

// D-layout quad -> tf32 A-layout frag for kf=nt
__device__ __forceinline__ void d2a_one(unsigned (&Akf)[4], const float v[4], int lane) {
  const int c = lane & 3;
  const int base = lane & ~3;
  const int s1 = base | (c >> 1);
  const int s2 = s1 + 2;
  const bool odd = (c & 1);
  float v0a = __shfl_sync(0xffffffffu, v[0], s1);
  float v1a = __shfl_sync(0xffffffffu, v[1], s1);
  float v2a = __shfl_sync(0xffffffffu, v[2], s1);
  float v3a = __shfl_sync(0xffffffffu, v[3], s1);
  float v0b = __shfl_sync(0xffffffffu, v[0], s2);
  float v1b = __shfl_sync(0xffffffffu, v[1], s2);
  float v2b = __shfl_sync(0xffffffffu, v[2], s2);
  float v3b = __shfl_sync(0xffffffffu, v[3], s2);
  Akf[0] = cvt_tf32(odd ? v1a : v0a);
  Akf[1] = cvt_tf32(odd ? v3a : v2a);
  Akf[2] = cvt_tf32(odd ? v1b : v0b);
  Akf[3] = cvt_tf32(odd ? v3b : v2b);
}

// hD (D layout) -> bf16 A16 frags (R6 identity: no shuffles)
__device__ __forceinline__ void build_a16(unsigned (&A16)[4][4], const float (&hD)[8][4]) {
#pragma unroll
  for (int nt = 0; nt < 8; nt++) {
    int kf = nt >> 1, r0 = (nt & 1) * 2;
    A16[kf][r0]     = packbf(hD[nt][0], hD[nt][1]);
    A16[kf][r0 + 1] = packbf(hD[nt][2], hD[nt][3]);
  }
}

// fill tf32 B-fragment bank (LDS.64 layout) from W[n][128] cols koff..+63
__device__ __forceinline__ void fill_frag(unsigned* dst, const float* __restrict__ W,
                                          int koff, int ntn, int tid) {
  int total = ntn * 8 * 32 * 2;
  for (int i = tid; i < total; i += NTHREADS) {
    int w = i & 1;
    int lane = (i >> 1) & 31;
    int kf = (i >> 6) & 7;
    int nt = i >> 9;
    int n = nt * 8 + (lane >> 2);
    int k = kf * 8 + (lane & 3) + w * 4;
    dst[i] = cvt_tf32(W[n * 128 + koff + k]);
  }
}

// fill bf16 k16 B-fragment bank from W[n][128] cols koff..+63
__device__ __forceinline__ void fill_frag16(unsigned* dst, const float* __restrict__ W,
                                            int koff, int ntn, int tid) {
  int total = ntn * 4 * 32;   // uint2 entries
  uint2* d2 = reinterpret_cast<uint2*>(dst);
  for (int i = tid; i < total; i += NTHREADS) {
    int lane = i & 31;
    int kf = (i >> 5) & 3;
    int nt = i >> 7;
    int n = nt * 8 + (lane >> 2);
    int kb = koff + kf * 16 + (lane & 3) * 2;
    uint2 v;
    v.x = packbf(W[n * 128 + kb],     W[n * 128 + kb + 1]);
    v.y = packbf(W[n * 128 + kb + 8], W[n * 128 + kb + 9]);
    d2[i] = v;
  }
}

__device__ __forceinline__ void build_xa(
    unsigned (&XA)[8][4], const float* __restrict__ pf, int pA, int pB, int c) {
  const float* xA = pf + (size_t)pA * 64;
  const float* xB = pf + (size_t)pB * 64;
#pragma unroll
  for (int kf = 0; kf < 8; kf++) {
    XA[kf][0] = cvt_tf32(__ldg(xA + kf * 8 + c));
    XA[kf][1] = cvt_tf32(__ldg(xB + kf * 8 + c));
    XA[kf][2] = cvt_tf32(__ldg(xA + kf * 8 + c + 4));
    XA[kf][3] = cvt_tf32(__ldg(xB + kf * 8 + c + 4));
  }
}

// bf16 x A16 frags
__device__ __forceinline__ void build_xa16(
    unsigned (&XA16)[4][4], const float* __restrict__ pf, int pA, int pB, int c) {
  const float2* xA = reinterpret_cast<const float2*>(pf + (size_t)pA * 64);
  const float2* xB = reinterpret_cast<const float2*>(pf + (size_t)pB * 64);
#pragma unroll
  for (int kf = 0; kf < 4; kf++) {
    float2 a0 = __ldg(xA + kf * 8 + c);
    float2 b0 = __ldg(xB + kf * 8 + c);
    float2 a1 = __ldg(xA + kf * 8 + c + 4);
    float2 b1 = __ldg(xB + kf * 8 + c + 4);
    XA16[kf][0] = packbf(a0.x, a0.y);
    XA16[kf][1] = packbf(b0.x, b0.y);
    XA16[kf][2] = packbf(a1.x, a1.y);
    XA16[kf][3] = packbf(b1.x, b1.y);
  }
}

__global__ __launch_bounds__(NTHREADS, 1)
void gru_mix17_kernel(
    const float* __restrict__ before, const float* __restrict__ after,
    const float* __restrict__ pf, const int* __restrict__ coords,
    const float* __restrict__ Wz, const float* __restrict__ bz,
    const float* __restrict__ Wr, const float* __restrict__ br,
    const float* __restrict__ Wq, const float* __restrict__ bq,
    const float* __restrict__ Wd1, const float* __restrict__ bd1,
    const float* __restrict__ Wd2, const float* __restrict__ bd2,
    float* __restrict__ out, int N, int total_pts)
{
  extern __shared__ char smem_raw[];
  Smem& s = *reinterpret_cast<Smem*>(smem_raw);
  const int tid = threadIdx.x;
  const int wid = tid >> 5, lane = tid & 31;
  const int g = lane >> 2, c = lane & 3;

  // ---- one-time weight fragment prep ----
  fill_frag16(s.wz_h16, Wz, 0, 8, tid);
  fill_frag16(s.wr_h16, Wr, 0, 8, tid);
  fill_frag16(s.wz_x16, Wz, 64, 8, tid);
  fill_frag16(s.wr_x16, Wr, 64, 8, tid);
  fill_frag(s.wq_h, Wq, 0, 8, tid);
  fill_frag(s.wq_x, Wq, 64, 8, tid);
  fill_frag(s.wd_h, Wd1, 0, 4, tid);
  fill_frag(s.wd_x, Wd1, 64, 4, tid);
  if (tid < 64) { s.bz[tid] = bz[tid]; s.br[tid] = br[tid]; s.bq[tid] = bq[tid]; }
  if (tid < 32) s.bd1[tid] = bd1[tid];
  if (tid < 96) s.Wd2[tid] = Wd2[tid];
  if (tid < 3)  s.bd2[tid] = bd2[tid];
  __syncthreads();

  const int ntiles = (total_pts + TILE_M - 1) / TILE_M;

  for (int tile = blockIdx.x; tile < ntiles; tile += gridDim.x) {
    const int ptA = tile * TILE_M + wid * 16 + g;   // rows 0-7
    const int ptB = ptA + 8;                         // rows 8-15
    const bool vA = ptA < total_pts, vB = ptB < total_pts;
    const int last = total_pts - 1;
    const int pA = vA ? ptA : last, pB = vB ? ptB : last;

    // ---- gather h in D layout (issued first; latency overlaps xproj phase) ----
    float hD[8][4];
    {
      const int* ccA = coords + (size_t)pA * 3;
      const int* ccB = coords + (size_t)pB * 3;
      int spA = ccA[0] * I_STRIDE + ccA[1] * J_STRIDE + ccA[2];
      int spB = ccB[0] * I_STRIDE + ccB[1] * J_STRIDE + ccB[2];
      const float* befA = before + (size_t)(pA / N) * B_STRIDE + (unsigned)spA;
      const float* aftA = after  + (size_t)(pA / N) * B_STRIDE + (unsigned)spA;
      const float* befB = before + (size_t)(pB / N) * B_STRIDE + (unsigned)spB;
      const float* aftB = after  + (size_t)(pB / N) * B_STRIDE + (unsigned)spB;
#pragma unroll
      for (int nt = 0; nt < 8; nt++) {
        int cb = (nt & 3) * 8 + 2 * c;
        const float* pa = (nt < 4) ? befA : aftA;
        const float* pb = (nt < 4) ? befB : aftB;
        hD[nt][0] = __ldg(pa + (size_t)cb * C_STRIDE);
        hD[nt][1] = __ldg(pa + (size_t)(cb + 1) * C_STRIDE);
        hD[nt][2] = __ldg(pb + (size_t)cb * C_STRIDE);
        hD[nt][3] = __ldg(pb + (size_t)(cb + 1) * C_STRIDE);
      }
    }

    // ---- x-projection GEMMs -> fp16 smem dumps (z,r bf16; q,dec tf32), biases folded ----
    {
      unsigned XA16[4][4];
      build_xa16(XA16, pf, pA, pB, c);
#pragma unroll
      for (int nt = 0; nt < 8; nt++) {
        int n0 = nt * 8 + 2 * c;
        float d[4];
        gemm4z(d, s.wz_x16, nt, lane, XA16);
        d[0] += s.bz[n0]; d[1] += s.bz[n0 + 1]; d[2] += s.bz[n0]; d[3] += s.bz[n0 + 1];
        xp_store(&s.xp[wid][nt][lane][0], d);
      }
#pragma unroll
      for (int nt = 0; nt < 8; nt++) {
        int n0 = nt * 8 + 2 * c;
        float d[4];
        gemm4z(d, s.wr_x16, nt, lane, XA16);
        d[0] += s.br[n0]; d[1] += s.br[n0 + 1]; d[2] += s.br[n0]; d[3] += s.br[n0 + 1];
        xp_store(&s.xp[wid][8 + nt][lane][0], d);
      }
    }
    {
      unsigned XA[8][4];
      build_xa(XA, pf, pA, pB, c);
#pragma unroll
      for (int nt = 0; nt < 8; nt++) {
        int n0 = nt * 8 + 2 * c;
        float d[4];
        gemm8z(d, s.wq_x, nt, lane, XA);
        d[0] += s.bq[n0]; d[1] += s.bq[n0 + 1]; d[2] += s.bq[n0]; d[3] += s.bq[n0 + 1];
        xp_store(&s.xp[wid][16 + nt][lane][0], d);
      }
#pragma unroll
      for (int nt = 0; nt < 4; nt++) {
        int n0 = nt * 8 + 2 * c;
        float d[4];
        gemm8z(d, s.wd_x, nt, lane, XA);
        d[0] += s.bd1[n0]; d[1] += s.bd1[n0 + 1]; d[2] += s.bd1[n0]; d[3] += s.bd1[n0 + 1];
        xp_store(&s.xp[wid][24 + nt][lane][0], d);
      }
    }

    // ---- 4 GRU iterations ----
#pragma unroll 1
    for (int it = 0; it < 4; it++) {
      unsigned A16[4][4];
      build_a16(A16, hD);          // bf16 h frags (no shuffles)
      unsigned R[8][4];
      // pass 1: r gate (bf16, reads A16) -> R = tf32(r*h) in A layout
      // xp load issued before the MMA chain so its LDS latency is hidden
#pragma unroll
      for (int nt = 0; nt < 8; nt++) {
        float xr[4], dr[4];
        xp_load(xr, &s.xp[wid][8 + nt][lane][0]);
        gemm4z(dr, s.wr_h16, nt, lane, A16);
        float rh[4];
#pragma unroll
        for (int j = 0; j < 4; j++) rh[j] = sigm(dr[j] + xr[j]) * hD[nt][j];
        d2a_one(R[nt], rh, lane);
      }
      // pass 2: z gate (bf16, reads A16) + q gate (tf32, reads R); update hD
#pragma unroll
      for (int nt = 0; nt < 8; nt++) {
        float xz[4], xq[4], dz[4], dq[4];
        xp_load(xz, &s.xp[wid][nt][lane][0]);
        xp_load(xq, &s.xp[wid][16 + nt][lane][0]);
        gemm4z(dz, s.wz_h16, nt, lane, A16);
        gemm8z(dq, s.wq_h, nt, lane, R);
#pragma unroll
        for (int j = 0; j < 4; j++)
          hD[nt][j] = fmaf(sigm(dz[j] + xz[j]), tanh_hw(dq[j] + xq[j]) - hD[nt][j], hD[nt][j]);
      }
    }

    // ---- decoder: hmid = gelu(Wd1h@h + dec_xp) (tf32, fast gelu) ----
    float hm[4][4];
    {
      unsigned Atf[8][4];
#pragma unroll
      for (int nt = 0; nt < 8; nt++) d2a_one(Atf[nt], hD[nt], lane);
#pragma unroll
      for (int nt = 0; nt < 4; nt++) {
        float xd[4], d[4];
        xp_load(xd, &s.xp[wid][24 + nt][lane][0]);
        gemm8z(d, s.wd_h, nt, lane, Atf);
#pragma unroll
        for (int j = 0; j < 4; j++)
          hm[nt][j] = gelu_fast(d[j] + xd[j]);
      }
    }

    // ---- flow = Wd2 @ hmid + bd2, quad reduction ----
    float fA[3] = {0.f, 0.f, 0.f}, fB[3] = {0.f, 0.f, 0.f};
#pragma unroll
    for (int nt = 0; nt < 4; nt++) {
      int n0 = nt * 8 + 2 * c;
#pragma unroll
      for (int o = 0; o < 3; o++) {
        float w0 = s.Wd2[o * 32 + n0], w1 = s.Wd2[o * 32 + n0 + 1];
        fA[o] += w0 * hm[nt][0] + w1 * hm[nt][1];
        fB[o] += w0 * hm[nt][2] + w1 * hm[nt][3];
      }
    }
#pragma unroll
    for (int o = 0; o < 3; o++) {
      fA[o] += __shfl_xor_sync(0xffffffffu, fA[o], 1);
      fA[o] += __shfl_xor_sync(0xffffffffu, fA[o], 2);
      fB[o] += __shfl_xor_sync(0xffffffffu, fB[o], 1);
      fB[o] += __shfl_xor_sync(0xffffffffu, fB[o], 2);
    }
    if (c < 3) {
      if (vA) out[(size_t)ptA * 3 + c] = fA[c] + s.bd2[c];
      if (vB) out[(size_t)ptB * 3 + c] = fB[c] + s.bd2[c];
    }
  }
}

extern "C" void kernel_launch(void* const* d_in, const int* in_sizes, int n_in,
                              void* d_out, int out_size) {
  const float* before = (const float*)d_in[0];
  const float* after  = (const float*)d_in[1];
  const float* pf     = (const float*)d_in[2];
  const int*   coords = (const int*)d_in[3];     // int32
  const float* Wz  = (const float*)d_in[4];
  const float* bz  = (const float*)d_in[5];
  const float* Wr  = (const float*)d_in[6];
  const float* br  = (const float*)d_in[7];
  const float* Wq  = (const float*)d_in[8];
  const float* bq  = (const float*)d_in[9];
  const float* Wd1 = (const float*)d_in[10];
  const float* bd1 = (const float*)d_in[11];
  const float* Wd2 = (const float*)d_in[12];
  const float* bd2 = (const float*)d_in[13];
  float* out = (float*)d_out;

  int B = in_sizes[0] / (int)(32u * 256u * 256u * 32u);
  if (B < 1) B = 1;
  int total_pts = in_sizes[3] / 3;
  int N = total_pts / B;

  cudaFuncSetAttribute(gru_mix17_kernel,
                       cudaFuncAttributeMaxDynamicSharedMemorySize,
                       (int)sizeof(Smem));

  gru_mix17_kernel<<<152, NTHREADS, sizeof(Smem)>>>(
      before, after, pf, coords, Wz, bz, Wr, br, Wq, bq,
      Wd1, bd1, Wd2, bd2, out, N, total_pts);
}